// round 1
// baseline (speedup 1.0000x reference)
#include <cuda_runtime.h>
#include <cuda_bf16.h>

// Problem constants
#define M_TOK   8192          // B*T = 4*2048
#define C_EMB   1024
#define C3      3072
#define N_HEADS 16
#define D_HEAD  64

// Scratch (static device globals — allocation-free per harness rules)
__device__ float g_qkv[(size_t)M_TOK * C3];    // 96 MB
__device__ float g_y[(size_t)M_TOK * C_EMB];   // 32 MB

// ---------------------------------------------------------------------------
// SGEMM: C[M,N] = A[M,K] @ B[K,N] + bias[N]
// 128x128 tile, BK=8, 256 threads, 8x8 per thread, reg prefetch of next tile.
// ---------------------------------------------------------------------------
#define BM 128
#define BN 128
#define BK 8
#define TM 8
#define TN 8

__global__ __launch_bounds__(256) void sgemm_bias_kernel(
    const float* __restrict__ A, const float* __restrict__ B,
    const float* __restrict__ bias, float* __restrict__ C,
    int M, int N, int K)
{
    __shared__ float As[BK][BM + 4];   // stride 132: conflict-free transposed stores
    __shared__ float Bs[BK][BN];

    const int tid = threadIdx.x;
    const int bm = blockIdx.y * BM;
    const int bn = blockIdx.x * BN;

    // A loader: one float4 per thread. row = tid>>1 (0..127), seg = tid&1
    const int a_row = tid >> 1;
    const int a_col = (tid & 1) * 4;
    // B loader: one float4 per thread. row = tid>>5 (0..7), col = (tid&31)*4
    const int b_row = tid >> 5;
    const int b_col = (tid & 31) * 4;

    const int tx = tid & 15;     // 0..15 -> N direction
    const int ty = tid >> 4;     // 0..15 -> M direction

    float acc[TM][TN];
#pragma unroll
    for (int i = 0; i < TM; i++)
#pragma unroll
        for (int j = 0; j < TN; j++) acc[i][j] = 0.f;

    const float* Aptr = A + (size_t)(bm + a_row) * K + a_col;
    const float* Bptr = B + (size_t)b_row * N + bn + b_col;

    float4 a4 = *(const float4*)Aptr;
    float4 b4 = *(const float4*)Bptr;

    for (int k0 = 0; k0 < K; k0 += BK) {
        // store current tile to smem
        As[a_col + 0][a_row] = a4.x;
        As[a_col + 1][a_row] = a4.y;
        As[a_col + 2][a_row] = a4.z;
        As[a_col + 3][a_row] = a4.w;
        *(float4*)&Bs[b_row][b_col] = b4;
        __syncthreads();

        // prefetch next tile into registers (overlaps with compute below)
        if (k0 + BK < K) {
            a4 = *(const float4*)(Aptr + k0 + BK);
            b4 = *(const float4*)(Bptr + (size_t)(k0 + BK) * N);
        }

#pragma unroll
        for (int kk = 0; kk < BK; kk++) {
            float ra[TM], rb[TN];
#pragma unroll
            for (int i = 0; i < TM; i++) ra[i] = As[kk][ty * TM + i];
#pragma unroll
            for (int j = 0; j < TN; j++) rb[j] = Bs[kk][tx * TN + j];
#pragma unroll
            for (int i = 0; i < TM; i++)
#pragma unroll
                for (int j = 0; j < TN; j++)
                    acc[i][j] += ra[i] * rb[j];
        }
        __syncthreads();
    }

    // epilogue: add bias, write float4s
#pragma unroll
    for (int i = 0; i < TM; i++) {
        const int row = bm + ty * TM + i;
#pragma unroll
        for (int j = 0; j < TN; j += 4) {
            const int col = bn + tx * TN + j;
            float4 v;
            v.x = acc[i][j + 0] + bias[col + 0];
            v.y = acc[i][j + 1] + bias[col + 1];
            v.z = acc[i][j + 2] + bias[col + 2];
            v.w = acc[i][j + 3] + bias[col + 3];
            *(float4*)&C[(size_t)row * N + col] = v;
        }
    }
}

// ---------------------------------------------------------------------------
// Flash attention (fp32, causal). One CTA per (q-tile of 128 rows, head, batch).
// Thread i owns q row i: q[64] and acc[64] in registers. K/V 64-row tiles in
// smem (broadcast reads). S tile staged in padded smem for the online-softmax
// second pass. Online softmax with rescale.
// ---------------------------------------------------------------------------
#define FQ 128
#define FK 64
#define SS_STRIDE 65   // conflict-free per-row access

__global__ __launch_bounds__(128, 1) void flash_attn_kernel(
    const float* __restrict__ qkv, float* __restrict__ y)
{
    extern __shared__ float sh[];
    float* Ss = sh;                        // FQ x SS_STRIDE
    float* Ks = sh + FQ * SS_STRIDE;       // FK x 64
    float* Vs = Ks + FK * D_HEAD;          // FK x 64

    const int i  = threadIdx.x;            // q row within tile
    const int qt = blockIdx.x;
    const int h  = blockIdx.y;
    const int b  = blockIdx.z;
    const int q0 = qt * FQ;

    const size_t rowQ = (size_t)b * 2048 + q0 + i;
    const float* qptr = qkv + rowQ * C3 + h * D_HEAD;

    float4 q[16];
#pragma unroll
    for (int d4 = 0; d4 < 16; d4++) q[d4] = *(const float4*)(qptr + d4 * 4);

    float4 acc[16];
#pragma unroll
    for (int d4 = 0; d4 < 16; d4++) acc[d4] = make_float4(0.f, 0.f, 0.f, 0.f);

    float m = -1e30f, l = 0.f;
    const float scale = 0.125f;            // 1/sqrt(64)
    const int qg = q0 + i;
    const int ktiles = 2 * qt + 2;         // covers k in [0, q0+128)

    for (int kt = 0; kt < ktiles; kt++) {
        const int k0 = kt * FK;

        __syncthreads();   // previous tile's K/V reads done before overwrite
        for (int idx = i; idx < FK * 16; idx += FQ) {
            const int r = idx >> 4, d4 = idx & 15;
            const float* base = qkv + ((size_t)b * 2048 + k0 + r) * C3 + h * D_HEAD;
            *(float4*)&Ks[r * D_HEAD + d4 * 4] = *(const float4*)(base + C_EMB + d4 * 4);
            *(float4*)&Vs[r * D_HEAD + d4 * 4] = *(const float4*)(base + 2 * C_EMB + d4 * 4);
        }
        __syncthreads();

        // pass 1: scores + tile max
        float tmax = -1e30f;
        for (int j = 0; j < FK; j++) {
            float s = 0.f;
#pragma unroll
            for (int d4 = 0; d4 < 16; d4++) {
                float4 kv = *(float4*)&Ks[j * D_HEAD + d4 * 4];
                s += q[d4].x * kv.x + q[d4].y * kv.y + q[d4].z * kv.z + q[d4].w * kv.w;
            }
            s *= scale;
            if (k0 + j > qg) s = -1e30f;   // causal mask
            tmax = fmaxf(tmax, s);
            Ss[i * SS_STRIDE + j] = s;
        }

        const float mnew = fmaxf(m, tmax);
        const float corr = __expf(m - mnew);
        m = mnew;
        l *= corr;
#pragma unroll
        for (int d4 = 0; d4 < 16; d4++) {
            acc[d4].x *= corr; acc[d4].y *= corr;
            acc[d4].z *= corr; acc[d4].w *= corr;
        }

        // pass 2: probs + PV
        for (int j = 0; j < FK; j++) {
            const float p = __expf(Ss[i * SS_STRIDE + j] - m);
            l += p;
#pragma unroll
            for (int d4 = 0; d4 < 16; d4++) {
                float4 vv = *(float4*)&Vs[j * D_HEAD + d4 * 4];
                acc[d4].x += p * vv.x; acc[d4].y += p * vv.y;
                acc[d4].z += p * vv.z; acc[d4].w += p * vv.w;
            }
        }
    }

    const float inv = 1.f / l;
    float* yp = y + rowQ * C_EMB + h * D_HEAD;
#pragma unroll
    for (int d4 = 0; d4 < 16; d4++) {
        float4 o = acc[d4];
        o.x *= inv; o.y *= inv; o.z *= inv; o.w *= inv;
        *(float4*)(yp + d4 * 4) = o;
    }
}

// ---------------------------------------------------------------------------
// Launch
// ---------------------------------------------------------------------------
extern "C" void kernel_launch(void* const* d_in, const int* in_sizes, int n_in,
                              void* d_out, int out_size)
{
    const float* x      = (const float*)d_in[0];
    const float* W_attn = (const float*)d_in[1];
    const float* b_attn = (const float*)d_in[2];
    const float* W_proj = (const float*)d_in[3];
    const float* b_proj = (const float*)d_in[4];
    float* out = (float*)d_out;

    float* qkv = nullptr;
    float* y   = nullptr;
    cudaGetSymbolAddress((void**)&qkv, g_qkv);
    cudaGetSymbolAddress((void**)&y, g_y);

    const int flash_smem = (FQ * SS_STRIDE + 2 * FK * D_HEAD) * (int)sizeof(float); // 66048
    cudaFuncSetAttribute(flash_attn_kernel,
                         cudaFuncAttributeMaxDynamicSharedMemorySize, flash_smem);

    // 1) QKV GEMM: [8192,1024] x [1024,3072] + b_attn
    {
        dim3 grid(C3 / BN, M_TOK / BM);
        sgemm_bias_kernel<<<grid, 256>>>(x, W_attn, b_attn, qkv, M_TOK, C3, C_EMB);
    }

    // 2) Flash attention -> y [8192,1024]
    {
        dim3 grid(2048 / FQ, N_HEADS, 4);
        flash_attn_kernel<<<grid, 128, flash_smem>>>(qkv, y);
    }

    // 3) Proj GEMM: [8192,1024] x [1024,1024] + b_proj -> out
    {
        dim3 grid(C_EMB / BN, M_TOK / BM);
        sgemm_bias_kernel<<<grid, 256>>>(y, W_proj, b_proj, out, M_TOK, C_EMB, C_EMB);
    }
}

// round 5
// speedup vs baseline: 1.3017x; 1.3017x over previous
#include <cuda_runtime.h>
#include <cuda_bf16.h>
#include <cstdint>

// Problem constants
#define M_TOK   8192          // B*T = 4*2048
#define C_EMB   1024
#define C3      3072
#define K3      3072          // tripled K for split GEMM (3 * C_EMB)
#define N_HEADS 16
#define D_HEAD  64

// ---------------------------------------------------------------------------
// Scratch (static device globals — allocation-free per harness rules)
// ---------------------------------------------------------------------------
__device__ float g_qkv[(size_t)M_TOK * C3];                 // 96 MB
__device__ float g_y[(size_t)M_TOK * C_EMB];                // 32 MB
__device__ __nv_bfloat16 g_a1[(size_t)M_TOK * K3];          // 48 MB  x split-cat
__device__ __nv_bfloat16 g_a2[(size_t)M_TOK * K3];          // 48 MB  y split-cat
__device__ __nv_bfloat16 g_wa[(size_t)C3 * K3];             // 18 MB  W_attn^T split-cat
__device__ __nv_bfloat16 g_wp[(size_t)C_EMB * K3];          //  6 MB  W_proj^T split-cat

// ---------------------------------------------------------------------------
// PTX helpers (baseline sm_103 — NO tcgen05 / 'a'-suffix features)
// ---------------------------------------------------------------------------
__device__ __forceinline__ uint32_t smemu32(const void* p) {
    return (uint32_t)__cvta_generic_to_shared(p);
}

#define CP_ASYNC_16(dst_u32, src_ptr) \
    asm volatile("cp.async.cg.shared.global [%0], [%1], 16;" \
        :: "r"(dst_u32), "l"(src_ptr))
#define CP_COMMIT() asm volatile("cp.async.commit_group;" ::: "memory")
#define CP_WAIT(n)  asm volatile("cp.async.wait_group %0;" :: "n"(n) : "memory")

#define LDMATRIX_X4(r0, r1, r2, r3, addr) \
    asm volatile("ldmatrix.sync.aligned.m8n8.x4.shared.b16 {%0,%1,%2,%3}, [%4];" \
        : "=r"(r0), "=r"(r1), "=r"(r2), "=r"(r3) : "r"(addr))
#define LDMATRIX_X2(r0, r1, addr) \
    asm volatile("ldmatrix.sync.aligned.m8n8.x2.shared.b16 {%0,%1}, [%2];" \
        : "=r"(r0), "=r"(r1) : "r"(addr))

#define MMA_BF16(d, a, b) \
    asm volatile("mma.sync.aligned.m16n8k16.row.col.f32.bf16.bf16.f32 " \
        "{%0,%1,%2,%3}, {%4,%5,%6,%7}, {%8,%9}, {%0,%1,%2,%3};" \
        : "+f"((d)[0]), "+f"((d)[1]), "+f"((d)[2]), "+f"((d)[3]) \
        : "r"((a)[0]), "r"((a)[1]), "r"((a)[2]), "r"((a)[3]), \
          "r"((b)[0]), "r"((b)[1]))

// ---------------------------------------------------------------------------
// split-cat: fp32 [M,K] -> bf16 [M,3K] = [hi | hi | lo]
// ---------------------------------------------------------------------------
__global__ void split_cat_kernel(const float* __restrict__ in,
                                 __nv_bfloat16* __restrict__ outp,
                                 int M, int K)
{
    int i = blockIdx.x * blockDim.x + threadIdx.x;
    if (i < M * K) {
        int m = i / K, k = i % K;
        float v = in[i];
        __nv_bfloat16 h = __float2bfloat16(v);
        __nv_bfloat16 l = __float2bfloat16(v - __bfloat162float(h));
        size_t base = (size_t)m * (3 * K);
        outp[base + k]          = h;
        outp[base + K + k]      = h;
        outp[base + 2 * K + k]  = l;
    }
}

// ---------------------------------------------------------------------------
// transpose-split-cat: fp32 W [K,N] row-major -> bf16 B' [N,3K] = [hi | lo | hi]
// (pairing: A seg0 hi * B seg0 hi, A seg1 hi * B seg1 lo, A seg2 lo * B seg2 hi)
// ---------------------------------------------------------------------------
__global__ void splitT_cat_kernel(const float* __restrict__ in,
                                  __nv_bfloat16* __restrict__ outp,
                                  int K, int N)
{
    __shared__ float t[32][33];
    const int n0 = blockIdx.x * 32, k0 = blockIdx.y * 32;
    const int tx = threadIdx.x, ty = threadIdx.y;
#pragma unroll
    for (int i = ty; i < 32; i += 8)
        t[i][tx] = in[(size_t)(k0 + i) * N + n0 + tx];
    __syncthreads();
#pragma unroll
    for (int i = ty; i < 32; i += 8) {
        float v = t[tx][i];   // = in[(k0+tx)*N + (n0+i)]
        __nv_bfloat16 h = __float2bfloat16(v);
        __nv_bfloat16 l = __float2bfloat16(v - __bfloat162float(h));
        size_t base = (size_t)(n0 + i) * (3 * K) + k0 + tx;
        outp[base]          = h;
        outp[base + K]      = l;
        outp[base + 2 * K]  = h;
    }
}

// ---------------------------------------------------------------------------
// bf16 mma.sync GEMM: C[M,N] = A[M,K]@B[N,K]^T + bias[N]
// CTA tile 128x128, BK=32, 256 threads (8 warps, 2x4), warp tile 64x32.
// cp.async double-buffered; ldmatrix fragments; fp32 accumulate.
// ---------------------------------------------------------------------------
#define GBM 128
#define GBN 128
#define GBK 32
#define LDSD 40   // smem row stride in bf16 elems (80B): conflict-free ldmatrix

__global__ __launch_bounds__(256) void hmma_gemm_kernel(
    const __nv_bfloat16* __restrict__ A,   // [M,K] row-major
    const __nv_bfloat16* __restrict__ B,   // [N,K] row-major
    const float* __restrict__ bias, float* __restrict__ C,
    int M, int N, int K)
{
    __shared__ __nv_bfloat16 As[2][GBM * LDSD];
    __shared__ __nv_bfloat16 Bs[2][GBN * LDSD];

    const int tid  = threadIdx.x;
    const int wid  = tid >> 5, lane = tid & 31;
    const int bm   = blockIdx.y * GBM, bn = blockIdx.x * GBN;
    const int wm   = (wid & 1) * 64;    // warp M offset within CTA
    const int wn   = (wid >> 1) * 32;   // warp N offset within CTA

    float acc[4][4][4];
#pragma unroll
    for (int mi = 0; mi < 4; mi++)
#pragma unroll
        for (int ni = 0; ni < 4; ni++)
#pragma unroll
            for (int r = 0; r < 4; r++) acc[mi][ni][r] = 0.f;

    const __nv_bfloat16* gA = A + (size_t)bm * K;
    const __nv_bfloat16* gB = B + (size_t)bn * K;

    // loader: 512 uint4 per operand tile / 256 threads = 2 each
    const int lr0 = tid >> 2;             // row for idx=tid       (0..63)
    const int lc  = (tid & 3) * 8;        // k-col (bf16 elems)
    // idx=tid+256 -> row lr0+64

    auto load_slab = [&](int stage, int k0) {
#pragma unroll
        for (int half = 0; half < 2; half++) {
            const int r = lr0 + half * 64;
            const size_t go = (size_t)r * K + k0 + lc;
            CP_ASYNC_16(smemu32(&As[stage][r * LDSD + lc]), gA + go);
            CP_ASYNC_16(smemu32(&Bs[stage][r * LDSD + lc]), gB + go);
        }
    };

    load_slab(0, 0);
    CP_COMMIT();

    const int NS = K / GBK;
    for (int s = 0; s < NS; s++) {
        if (s + 1 < NS) {
            load_slab((s + 1) & 1, (s + 1) * GBK);
            CP_COMMIT();
            CP_WAIT(1);
        } else {
            CP_WAIT(0);
        }
        __syncthreads();

        const __nv_bfloat16* as = As[s & 1];
        const __nv_bfloat16* bs = Bs[s & 1];

#pragma unroll
        for (int kk = 0; kk < GBK; kk += 16) {
            uint32_t af[4][4], bf[4][2];
#pragma unroll
            for (int mi = 0; mi < 4; mi++) {
                const int row = wm + mi * 16 + (lane & 15);
                const int col = kk + (lane >> 4) * 8;
                LDMATRIX_X4(af[mi][0], af[mi][1], af[mi][2], af[mi][3],
                            smemu32(&as[row * LDSD + col]));
            }
#pragma unroll
            for (int ni = 0; ni < 4; ni++) {
                const int nrow = wn + ni * 8 + (lane & 7);
                const int col  = kk + ((lane >> 3) & 1) * 8;
                LDMATRIX_X2(bf[ni][0], bf[ni][1],
                            smemu32(&bs[nrow * LDSD + col]));
            }
#pragma unroll
            for (int mi = 0; mi < 4; mi++)
#pragma unroll
                for (int ni = 0; ni < 4; ni++)
                    MMA_BF16(acc[mi][ni], af[mi], bf[ni]);
        }
        __syncthreads();
    }

    // epilogue: mma fragment -> global with bias
    const int gq = lane >> 2;           // quad row (0..7)
    const int qp = (lane & 3) * 2;      // col pair
#pragma unroll
    for (int mi = 0; mi < 4; mi++) {
        const int r0 = bm + wm + mi * 16 + gq;
#pragma unroll
        for (int ni = 0; ni < 4; ni++) {
            const int col = bn + wn + ni * 8 + qp;
            const float bx = __ldg(&bias[col]), by = __ldg(&bias[col + 1]);
            float2 v0 = make_float2(acc[mi][ni][0] + bx, acc[mi][ni][1] + by);
            float2 v1 = make_float2(acc[mi][ni][2] + bx, acc[mi][ni][3] + by);
            *(float2*)&C[(size_t)r0 * N + col]        = v0;
            *(float2*)&C[(size_t)(r0 + 8) * N + col]  = v1;
        }
    }
}

// ---------------------------------------------------------------------------
// Flash attention (fp32, causal) — unchanged from R0 (passing).
// ---------------------------------------------------------------------------
#define FQ 128
#define FK 64
#define SS_STRIDE 65

__global__ __launch_bounds__(128, 1) void flash_attn_kernel(
    const float* __restrict__ qkv, float* __restrict__ y)
{
    extern __shared__ float sh[];
    float* Ss = sh;                        // FQ x SS_STRIDE
    float* Ks = sh + FQ * SS_STRIDE;       // FK x 64
    float* Vs = Ks + FK * D_HEAD;          // FK x 64

    const int i  = threadIdx.x;
    const int qt = blockIdx.x;
    const int h  = blockIdx.y;
    const int b  = blockIdx.z;
    const int q0 = qt * FQ;

    const size_t rowQ = (size_t)b * 2048 + q0 + i;
    const float* qptr = qkv + rowQ * C3 + h * D_HEAD;

    float4 q[16];
#pragma unroll
    for (int d4 = 0; d4 < 16; d4++) q[d4] = *(const float4*)(qptr + d4 * 4);

    float4 acc[16];
#pragma unroll
    for (int d4 = 0; d4 < 16; d4++) acc[d4] = make_float4(0.f, 0.f, 0.f, 0.f);

    float m = -1e30f, l = 0.f;
    const float scale = 0.125f;
    const int qg = q0 + i;
    const int ktiles = 2 * qt + 2;

    for (int kt = 0; kt < ktiles; kt++) {
        const int k0 = kt * FK;

        __syncthreads();
        for (int idx = i; idx < FK * 16; idx += FQ) {
            const int r = idx >> 4, d4 = idx & 15;
            const float* base = qkv + ((size_t)b * 2048 + k0 + r) * C3 + h * D_HEAD;
            *(float4*)&Ks[r * D_HEAD + d4 * 4] = *(const float4*)(base + C_EMB + d4 * 4);
            *(float4*)&Vs[r * D_HEAD + d4 * 4] = *(const float4*)(base + 2 * C_EMB + d4 * 4);
        }
        __syncthreads();

        float tmax = -1e30f;
        for (int j = 0; j < FK; j++) {
            float s = 0.f;
#pragma unroll
            for (int d4 = 0; d4 < 16; d4++) {
                float4 kv = *(float4*)&Ks[j * D_HEAD + d4 * 4];
                s += q[d4].x * kv.x + q[d4].y * kv.y + q[d4].z * kv.z + q[d4].w * kv.w;
            }
            s *= scale;
            if (k0 + j > qg) s = -1e30f;
            tmax = fmaxf(tmax, s);
            Ss[i * SS_STRIDE + j] = s;
        }

        const float mnew = fmaxf(m, tmax);
        const float corr = __expf(m - mnew);
        m = mnew;
        l *= corr;
#pragma unroll
        for (int d4 = 0; d4 < 16; d4++) {
            acc[d4].x *= corr; acc[d4].y *= corr;
            acc[d4].z *= corr; acc[d4].w *= corr;
        }

        for (int j = 0; j < FK; j++) {
            const float p = __expf(Ss[i * SS_STRIDE + j] - m);
            l += p;
#pragma unroll
            for (int d4 = 0; d4 < 16; d4++) {
                float4 vv = *(float4*)&Vs[j * D_HEAD + d4 * 4];
                acc[d4].x += p * vv.x; acc[d4].y += p * vv.y;
                acc[d4].z += p * vv.z; acc[d4].w += p * vv.w;
            }
        }
    }

    const float inv = 1.f / l;
    float* yp = y + rowQ * C_EMB + h * D_HEAD;
#pragma unroll
    for (int d4 = 0; d4 < 16; d4++) {
        float4 o = acc[d4];
        o.x *= inv; o.y *= inv; o.z *= inv; o.w *= inv;
        *(float4*)(yp + d4 * 4) = o;
    }
}

// ---------------------------------------------------------------------------
// Launch
// ---------------------------------------------------------------------------
extern "C" void kernel_launch(void* const* d_in, const int* in_sizes, int n_in,
                              void* d_out, int out_size)
{
    const float* x      = (const float*)d_in[0];
    const float* W_attn = (const float*)d_in[1];
    const float* b_attn = (const float*)d_in[2];
    const float* W_proj = (const float*)d_in[3];
    const float* b_proj = (const float*)d_in[4];
    float* out = (float*)d_out;

    float *qkv, *y;
    __nv_bfloat16 *a1, *a2, *wa, *wp;
    cudaGetSymbolAddress((void**)&qkv, g_qkv);
    cudaGetSymbolAddress((void**)&y, g_y);
    cudaGetSymbolAddress((void**)&a1, g_a1);
    cudaGetSymbolAddress((void**)&a2, g_a2);
    cudaGetSymbolAddress((void**)&wa, g_wa);
    cudaGetSymbolAddress((void**)&wp, g_wp);

    const int flash_smem = (FQ * SS_STRIDE + 2 * FK * D_HEAD) * (int)sizeof(float);
    cudaFuncSetAttribute(flash_attn_kernel,
                         cudaFuncAttributeMaxDynamicSharedMemorySize, flash_smem);

    // 0a) split-cat x -> a1 [8192, 3072] = [hi|hi|lo]
    {
        int n = M_TOK * C_EMB;
        split_cat_kernel<<<(n + 255) / 256, 256>>>(x, a1, M_TOK, C_EMB);
    }
    // 0b) transpose-split-cat weights -> [N, 3K] = [hi|lo|hi]
    {
        dim3 grid(C3 / 32, C_EMB / 32);
        splitT_cat_kernel<<<grid, dim3(32, 8)>>>(W_attn, wa, C_EMB, C3);
    }
    {
        dim3 grid(C_EMB / 32, C_EMB / 32);
        splitT_cat_kernel<<<grid, dim3(32, 8)>>>(W_proj, wp, C_EMB, C_EMB);
    }

    // 1) QKV GEMM (mma.sync bf16, K'=3072): -> qkv [8192, 3072]
    {
        dim3 grid(C3 / GBN, M_TOK / GBM);
        hmma_gemm_kernel<<<grid, 256>>>(a1, wa, b_attn, qkv, M_TOK, C3, K3);
    }

    // 2) Flash attention -> y [8192, 1024]
    {
        dim3 grid(2048 / FQ, N_HEADS, 4);
        flash_attn_kernel<<<grid, 128, flash_smem>>>(qkv, y);
    }

    // 3) split-cat y, then proj GEMM -> out
    {
        int n = M_TOK * C_EMB;
        split_cat_kernel<<<(n + 255) / 256, 256>>>(y, a2, M_TOK, C_EMB);
    }
    {
        dim3 grid(C_EMB / GBN, M_TOK / GBM);
        hmma_gemm_kernel<<<grid, 256>>>(a2, wp, b_proj, out, M_TOK, C_EMB, K3);
    }
}

// round 7
// speedup vs baseline: 2.5247x; 1.9396x over previous
#include <cuda_runtime.h>
#include <cuda_bf16.h>
#include <cstdint>

// Problem constants
#define M_TOK   8192          // B*T = 4*2048
#define C_EMB   1024
#define C3      3072
#define K3      3072          // tripled K for split GEMM (3 * C_EMB)
#define N_HEADS 16
#define D_HEAD  64

// ---------------------------------------------------------------------------
// Scratch (static device globals — allocation-free per harness rules)
// ---------------------------------------------------------------------------
__device__ __nv_bfloat16 g_a1[(size_t)M_TOK * K3];          // 48 MB  x split-cat
__device__ __nv_bfloat16 g_a2[(size_t)M_TOK * K3];          // 48 MB  y split-cat (flash out)
__device__ __nv_bfloat16 g_wa[(size_t)C3 * K3];             // 18 MB  W_attn^T split-cat
__device__ __nv_bfloat16 g_wp[(size_t)C_EMB * K3];          //  6 MB  W_proj^T split-cat
__device__ __nv_bfloat16 g_qkvh[(size_t)M_TOK * C3];        // 48 MB  qkv hi
__device__ __nv_bfloat16 g_qkvl[(size_t)M_TOK * C3];        // 48 MB  qkv lo

// ---------------------------------------------------------------------------
// PTX helpers (baseline sm_103 — NO tcgen05 / 'a'-suffix features)
// ---------------------------------------------------------------------------
__device__ __forceinline__ uint32_t smemu32(const void* p) {
    return (uint32_t)__cvta_generic_to_shared(p);
}

#define CP_ASYNC_16(dst_u32, src_ptr) \
    asm volatile("cp.async.cg.shared.global [%0], [%1], 16;" \
        :: "r"(dst_u32), "l"(src_ptr))
#define CP_COMMIT() asm volatile("cp.async.commit_group;" ::: "memory")
#define CP_WAIT(n)  asm volatile("cp.async.wait_group %0;" :: "n"(n) : "memory")

#define LDMATRIX_X4(r0, r1, r2, r3, addr) \
    asm volatile("ldmatrix.sync.aligned.m8n8.x4.shared.b16 {%0,%1,%2,%3}, [%4];" \
        : "=r"(r0), "=r"(r1), "=r"(r2), "=r"(r3) : "r"(addr))
#define LDMATRIX_X2(r0, r1, addr) \
    asm volatile("ldmatrix.sync.aligned.m8n8.x2.shared.b16 {%0,%1}, [%2];" \
        : "=r"(r0), "=r"(r1) : "r"(addr))
#define LDMATRIX_X2_TRANS(r0, r1, addr) \
    asm volatile("ldmatrix.sync.aligned.m8n8.x2.trans.shared.b16 {%0,%1}, [%2];" \
        : "=r"(r0), "=r"(r1) : "r"(addr))

#define MMA_BF16(d, a, b) \
    asm volatile("mma.sync.aligned.m16n8k16.row.col.f32.bf16.bf16.f32 " \
        "{%0,%1,%2,%3}, {%4,%5,%6,%7}, {%8,%9}, {%0,%1,%2,%3};" \
        : "+f"((d)[0]), "+f"((d)[1]), "+f"((d)[2]), "+f"((d)[3]) \
        : "r"((a)[0]), "r"((a)[1]), "r"((a)[2]), "r"((a)[3]), \
          "r"((b)[0]), "r"((b)[1]))

// split two floats into packed bf16x2 hi and lo
__device__ __forceinline__ void split2(float x, float y, uint32_t& hi, uint32_t& lo) {
    __nv_bfloat16 hx = __float2bfloat16(x), hy = __float2bfloat16(y);
    __nv_bfloat16 lx = __float2bfloat16(x - __bfloat162float(hx));
    __nv_bfloat16 ly = __float2bfloat16(y - __bfloat162float(hy));
    __nv_bfloat162 hp = __nv_bfloat162(hx, hy), lp = __nv_bfloat162(lx, ly);
    hi = *(uint32_t*)&hp;
    lo = *(uint32_t*)&lp;
}

// ---------------------------------------------------------------------------
// split-cat: fp32 [M,K] -> bf16 [M,3K] = [hi | hi | lo]
// ---------------------------------------------------------------------------
__global__ void split_cat_kernel(const float* __restrict__ in,
                                 __nv_bfloat16* __restrict__ outp,
                                 int M, int K)
{
    int i = blockIdx.x * blockDim.x + threadIdx.x;
    if (i < M * K) {
        int m = i / K, k = i % K;
        float v = in[i];
        __nv_bfloat16 h = __float2bfloat16(v);
        __nv_bfloat16 l = __float2bfloat16(v - __bfloat162float(h));
        size_t base = (size_t)m * (3 * K);
        outp[base + k]          = h;
        outp[base + K + k]      = h;
        outp[base + 2 * K + k]  = l;
    }
}

// ---------------------------------------------------------------------------
// transpose-split-cat: fp32 W [K,N] -> bf16 B' [N,3K] = [hi | lo | hi]
// ---------------------------------------------------------------------------
__global__ void splitT_cat_kernel(const float* __restrict__ in,
                                  __nv_bfloat16* __restrict__ outp,
                                  int K, int N)
{
    __shared__ float t[32][33];
    const int n0 = blockIdx.x * 32, k0 = blockIdx.y * 32;
    const int tx = threadIdx.x, ty = threadIdx.y;
#pragma unroll
    for (int i = ty; i < 32; i += 8)
        t[i][tx] = in[(size_t)(k0 + i) * N + n0 + tx];
    __syncthreads();
#pragma unroll
    for (int i = ty; i < 32; i += 8) {
        float v = t[tx][i];
        __nv_bfloat16 h = __float2bfloat16(v);
        __nv_bfloat16 l = __float2bfloat16(v - __bfloat162float(h));
        size_t base = (size_t)(n0 + i) * (3 * K) + k0 + tx;
        outp[base]          = h;
        outp[base + K]      = l;
        outp[base + 2 * K]  = h;
    }
}

// ---------------------------------------------------------------------------
// bf16 mma.sync GEMM: C = A[M,K]@B[N,K]^T + bias
// BF16OUT=false: write fp32 C.  BF16OUT=true: write bf16 hi/lo (Ch, Cl).
// ---------------------------------------------------------------------------
#define GBM 128
#define GBN 128
#define GBK 32
#define LDSD 40

template<bool BF16OUT>
__global__ __launch_bounds__(256) void hmma_gemm_kernel(
    const __nv_bfloat16* __restrict__ A,
    const __nv_bfloat16* __restrict__ B,
    const float* __restrict__ bias, float* __restrict__ C,
    __nv_bfloat16* __restrict__ Ch, __nv_bfloat16* __restrict__ Cl,
    int M, int N, int K)
{
    __shared__ __nv_bfloat16 As[2][GBM * LDSD];
    __shared__ __nv_bfloat16 Bs[2][GBN * LDSD];

    const int tid  = threadIdx.x;
    const int wid  = tid >> 5, lane = tid & 31;
    const int bm   = blockIdx.y * GBM, bn = blockIdx.x * GBN;
    const int wm   = (wid & 1) * 64;
    const int wn   = (wid >> 1) * 32;

    float acc[4][4][4];
#pragma unroll
    for (int mi = 0; mi < 4; mi++)
#pragma unroll
        for (int ni = 0; ni < 4; ni++)
#pragma unroll
            for (int r = 0; r < 4; r++) acc[mi][ni][r] = 0.f;

    const __nv_bfloat16* gA = A + (size_t)bm * K;
    const __nv_bfloat16* gB = B + (size_t)bn * K;

    const int lr0 = tid >> 2;
    const int lc  = (tid & 3) * 8;

    auto load_slab = [&](int stage, int k0) {
#pragma unroll
        for (int half = 0; half < 2; half++) {
            const int r = lr0 + half * 64;
            const size_t go = (size_t)r * K + k0 + lc;
            CP_ASYNC_16(smemu32(&As[stage][r * LDSD + lc]), gA + go);
            CP_ASYNC_16(smemu32(&Bs[stage][r * LDSD + lc]), gB + go);
        }
    };

    load_slab(0, 0);
    CP_COMMIT();

    const int NS = K / GBK;
    for (int s = 0; s < NS; s++) {
        if (s + 1 < NS) {
            load_slab((s + 1) & 1, (s + 1) * GBK);
            CP_COMMIT();
            CP_WAIT(1);
        } else {
            CP_WAIT(0);
        }
        __syncthreads();

        const __nv_bfloat16* as = As[s & 1];
        const __nv_bfloat16* bs = Bs[s & 1];

#pragma unroll
        for (int kk = 0; kk < GBK; kk += 16) {
            uint32_t af[4][4], bf[4][2];
#pragma unroll
            for (int mi = 0; mi < 4; mi++) {
                const int row = wm + mi * 16 + (lane & 15);
                const int col = kk + (lane >> 4) * 8;
                LDMATRIX_X4(af[mi][0], af[mi][1], af[mi][2], af[mi][3],
                            smemu32(&as[row * LDSD + col]));
            }
#pragma unroll
            for (int ni = 0; ni < 4; ni++) {
                const int nrow = wn + ni * 8 + (lane & 7);
                const int col  = kk + ((lane >> 3) & 1) * 8;
                LDMATRIX_X2(bf[ni][0], bf[ni][1],
                            smemu32(&bs[nrow * LDSD + col]));
            }
#pragma unroll
            for (int mi = 0; mi < 4; mi++)
#pragma unroll
                for (int ni = 0; ni < 4; ni++)
                    MMA_BF16(acc[mi][ni], af[mi], bf[ni]);
        }
        __syncthreads();
    }

    const int gq = lane >> 2;
    const int qp = (lane & 3) * 2;
#pragma unroll
    for (int mi = 0; mi < 4; mi++) {
        const int r0 = bm + wm + mi * 16 + gq;
#pragma unroll
        for (int ni = 0; ni < 4; ni++) {
            const int col = bn + wn + ni * 8 + qp;
            const float bx = __ldg(&bias[col]), by = __ldg(&bias[col + 1]);
            float v0 = acc[mi][ni][0] + bx, v1 = acc[mi][ni][1] + by;
            float v2 = acc[mi][ni][2] + bx, v3 = acc[mi][ni][3] + by;
            if (!BF16OUT) {
                *(float2*)&C[(size_t)r0 * N + col]       = make_float2(v0, v1);
                *(float2*)&C[(size_t)(r0 + 8) * N + col] = make_float2(v2, v3);
            } else {
                uint32_t h0, l0, h1, l1;
                split2(v0, v1, h0, l0);
                split2(v2, v3, h1, l1);
                *(uint32_t*)&Ch[(size_t)r0 * N + col]       = h0;
                *(uint32_t*)&Cl[(size_t)r0 * N + col]       = l0;
                *(uint32_t*)&Ch[(size_t)(r0 + 8) * N + col] = h1;
                *(uint32_t*)&Cl[(size_t)(r0 + 8) * N + col] = l1;
            }
        }
    }
}

// ---------------------------------------------------------------------------
// Flash attention, HMMA bf16 split. 1 CTA per (q-tile 128, head, batch).
// 8 warps x 16 q-rows. K/V tiles of 64 keys, hi/lo, double-buffered cp.async.
// Output written directly in split-cat [hi|hi|lo] layout for the proj GEMM.
// ---------------------------------------------------------------------------
#define FP 72   // padded smem row stride (bf16) — conflict-free ldmatrix

__global__ __launch_bounds__(256) void flash_hmma_kernel(
    const __nv_bfloat16* __restrict__ qkh,
    const __nv_bfloat16* __restrict__ qkl,
    __nv_bfloat16* __restrict__ ycat)
{
    extern __shared__ __nv_bfloat16 sm[];
    __nv_bfloat16* sQh = sm;                     // 128*FP
    __nv_bfloat16* sQl = sQh + 128 * FP;
    __nv_bfloat16* sKh = sQl + 128 * FP;         // 2 stages of 64*FP
    __nv_bfloat16* sKl = sKh + 2 * 64 * FP;
    __nv_bfloat16* sVh = sKl + 2 * 64 * FP;
    __nv_bfloat16* sVl = sVh + 2 * 64 * FP;

    const int tid = threadIdx.x, wid = tid >> 5, lane = tid & 31;
    const int qt = (int)gridDim.x - 1 - (int)blockIdx.x;   // heavy tiles first
    const int h = blockIdx.y, b = blockIdx.z;
    const int q0 = qt * 128;
    const size_t tokQ = (size_t)b * 2048 + q0;
    const int colQ = h * 64;

    // Q tile (hi+lo) via cp.async
    for (int i = tid; i < 1024; i += 256) {
        const int r = i >> 3, c = (i & 7) * 8;
        const size_t g = (tokQ + r) * C3 + colQ + c;
        CP_ASYNC_16(smemu32(&sQh[r * FP + c]), qkh + g);
        CP_ASYNC_16(smemu32(&sQl[r * FP + c]), qkl + g);
    }
    auto load_kv = [&](int st, int k0) {
        __nv_bfloat16* kh = sKh + st * 64 * FP;
        __nv_bfloat16* kl = sKl + st * 64 * FP;
        __nv_bfloat16* vh = sVh + st * 64 * FP;
        __nv_bfloat16* vl = sVl + st * 64 * FP;
        for (int i = tid; i < 512; i += 256) {
            const int r = i >> 3, c = (i & 7) * 8;
            const size_t gk = ((size_t)b * 2048 + k0 + r) * C3 + C_EMB + colQ + c;
            const size_t gv = gk + C_EMB;
            CP_ASYNC_16(smemu32(&kh[r * FP + c]), qkh + gk);
            CP_ASYNC_16(smemu32(&kl[r * FP + c]), qkl + gk);
            CP_ASYNC_16(smemu32(&vh[r * FP + c]), qkh + gv);
            CP_ASYNC_16(smemu32(&vl[r * FP + c]), qkl + gv);
        }
    };
    load_kv(0, 0);
    CP_COMMIT();

    float o[8][4];
#pragma unroll
    for (int dt = 0; dt < 8; dt++)
#pragma unroll
        for (int e = 0; e < 4; e++) o[dt][e] = 0.f;
    float m0 = -1e30f, m1 = -1e30f, l0 = 0.f, l1 = 0.f;
    uint32_t qfh[4][4], qfl[4][4];

    const int gq = lane >> 2, qp2 = (lane & 3) * 2;
    const int row0 = q0 + wid * 16 + gq, row1 = row0 + 8;
    const int ktiles = 2 * qt + 2;

    for (int kt = 0; kt < ktiles; kt++) {
        if (kt + 1 < ktiles) {
            load_kv((kt + 1) & 1, (kt + 1) * 64);
            CP_COMMIT();
            CP_WAIT(1);
        } else {
            CP_WAIT(0);
        }
        __syncthreads();

        if (kt == 0) {
            // Q fragments (once)
#pragma unroll
            for (int ks = 0; ks < 4; ks++) {
                const int qrow = wid * 16 + (lane & 15);
                const int qcol = ks * 16 + (lane >> 4) * 8;
                LDMATRIX_X4(qfh[ks][0], qfh[ks][1], qfh[ks][2], qfh[ks][3],
                            smemu32(&sQh[qrow * FP + qcol]));
                LDMATRIX_X4(qfl[ks][0], qfl[ks][1], qfl[ks][2], qfl[ks][3],
                            smemu32(&sQl[qrow * FP + qcol]));
            }
        }

        const int st = kt & 1, k0 = kt * 64;
        const __nv_bfloat16* kh = sKh + st * 64 * FP;
        const __nv_bfloat16* kl = sKl + st * 64 * FP;
        const __nv_bfloat16* vh = sVh + st * 64 * FP;
        const __nv_bfloat16* vl = sVl + st * 64 * FP;

        // S = Q@K^T (split: hh + lh + hl), fp32 accum
        float s[8][4];
#pragma unroll
        for (int nt = 0; nt < 8; nt++)
#pragma unroll
            for (int e = 0; e < 4; e++) s[nt][e] = 0.f;

#pragma unroll
        for (int ks = 0; ks < 4; ks++) {
#pragma unroll
            for (int nt = 0; nt < 8; nt++) {
                uint32_t bh[2], bl[2];
                const int krow = nt * 8 + (lane & 7);
                const int kcol = ks * 16 + ((lane >> 3) & 1) * 8;
                LDMATRIX_X2(bh[0], bh[1], smemu32(&kh[krow * FP + kcol]));
                LDMATRIX_X2(bl[0], bl[1], smemu32(&kl[krow * FP + kcol]));
                MMA_BF16(s[nt], qfh[ks], bh);
                MMA_BF16(s[nt], qfl[ks], bh);
                MMA_BF16(s[nt], qfh[ks], bl);
            }
        }

        // scale + causal mask + row max
        const bool domask = (kt >= 2 * qt);
        float t0 = -1e30f, t1 = -1e30f;
#pragma unroll
        for (int nt = 0; nt < 8; nt++) {
#pragma unroll
            for (int e = 0; e < 4; e++) s[nt][e] *= 0.125f;
            if (domask) {
                const int c0 = k0 + nt * 8 + qp2;
                if (c0 > row0)     s[nt][0] = -1e30f;
                if (c0 + 1 > row0) s[nt][1] = -1e30f;
                if (c0 > row1)     s[nt][2] = -1e30f;
                if (c0 + 1 > row1) s[nt][3] = -1e30f;
            }
            t0 = fmaxf(t0, fmaxf(s[nt][0], s[nt][1]));
            t1 = fmaxf(t1, fmaxf(s[nt][2], s[nt][3]));
        }
        t0 = fmaxf(t0, __shfl_xor_sync(0xFFFFFFFFu, t0, 1));
        t0 = fmaxf(t0, __shfl_xor_sync(0xFFFFFFFFu, t0, 2));
        t1 = fmaxf(t1, __shfl_xor_sync(0xFFFFFFFFu, t1, 1));
        t1 = fmaxf(t1, __shfl_xor_sync(0xFFFFFFFFu, t1, 2));

        const float mn0 = fmaxf(m0, t0), mn1 = fmaxf(m1, t1);
        const float cr0 = __expf(m0 - mn0), cr1 = __expf(m1 - mn1);
        m0 = mn0; m1 = mn1;

        float sum0 = 0.f, sum1 = 0.f;
#pragma unroll
        for (int nt = 0; nt < 8; nt++) {
            s[nt][0] = __expf(s[nt][0] - m0);
            s[nt][1] = __expf(s[nt][1] - m0);
            s[nt][2] = __expf(s[nt][2] - m1);
            s[nt][3] = __expf(s[nt][3] - m1);
            sum0 += s[nt][0] + s[nt][1];
            sum1 += s[nt][2] + s[nt][3];
        }
        sum0 += __shfl_xor_sync(0xFFFFFFFFu, sum0, 1);
        sum0 += __shfl_xor_sync(0xFFFFFFFFu, sum0, 2);
        sum1 += __shfl_xor_sync(0xFFFFFFFFu, sum1, 1);
        sum1 += __shfl_xor_sync(0xFFFFFFFFu, sum1, 2);
        l0 = l0 * cr0 + sum0;
        l1 = l1 * cr1 + sum1;

#pragma unroll
        for (int dt = 0; dt < 8; dt++) {
            o[dt][0] *= cr0; o[dt][1] *= cr0;
            o[dt][2] *= cr1; o[dt][3] *= cr1;
        }

        // O += P@V (split: hh + lh + hl). P from S fragments (C->A reuse).
#pragma unroll
        for (int t = 0; t < 4; t++) {
            uint32_t ah[4], al[4];
            split2(s[2 * t][0],     s[2 * t][1],     ah[0], al[0]);
            split2(s[2 * t][2],     s[2 * t][3],     ah[1], al[1]);
            split2(s[2 * t + 1][0], s[2 * t + 1][1], ah[2], al[2]);
            split2(s[2 * t + 1][2], s[2 * t + 1][3], ah[3], al[3]);
#pragma unroll
            for (int dt = 0; dt < 8; dt++) {
                uint32_t bvh[2], bvl[2];
                const int vrow = t * 16 + (lane & 15);
                LDMATRIX_X2_TRANS(bvh[0], bvh[1], smemu32(&vh[vrow * FP + dt * 8]));
                LDMATRIX_X2_TRANS(bvl[0], bvl[1], smemu32(&vl[vrow * FP + dt * 8]));
                MMA_BF16(o[dt], ah, bvh);
                MMA_BF16(o[dt], al, bvh);
                MMA_BF16(o[dt], ah, bvl);
            }
        }
        __syncthreads();
    }

    // epilogue: normalize, write split-cat [hi|hi|lo]
    const float inv0 = 1.f / l0, inv1 = 1.f / l1;
    const size_t tok0 = tokQ + wid * 16 + gq;
    const size_t base0 = tok0 * K3 + colQ;
    const size_t base1 = (tok0 + 8) * K3 + colQ;
#pragma unroll
    for (int dt = 0; dt < 8; dt++) {
        const int c = dt * 8 + qp2;
        uint32_t h0, lo0, h1, lo1;
        split2(o[dt][0] * inv0, o[dt][1] * inv0, h0, lo0);
        split2(o[dt][2] * inv1, o[dt][3] * inv1, h1, lo1);
        *(uint32_t*)&ycat[base0 + c]              = h0;
        *(uint32_t*)&ycat[base0 + C_EMB + c]      = h0;
        *(uint32_t*)&ycat[base0 + 2 * C_EMB + c]  = lo0;
        *(uint32_t*)&ycat[base1 + c]              = h1;
        *(uint32_t*)&ycat[base1 + C_EMB + c]      = h1;
        *(uint32_t*)&ycat[base1 + 2 * C_EMB + c]  = lo1;
    }
}

// ---------------------------------------------------------------------------
// Launch
// ---------------------------------------------------------------------------
extern "C" void kernel_launch(void* const* d_in, const int* in_sizes, int n_in,
                              void* d_out, int out_size)
{
    const float* x      = (const float*)d_in[0];
    const float* W_attn = (const float*)d_in[1];
    const float* b_attn = (const float*)d_in[2];
    const float* W_proj = (const float*)d_in[3];
    const float* b_proj = (const float*)d_in[4];
    float* out = (float*)d_out;

    __nv_bfloat16 *a1, *a2, *wa, *wp, *qh, *ql;
    cudaGetSymbolAddress((void**)&a1, g_a1);
    cudaGetSymbolAddress((void**)&a2, g_a2);
    cudaGetSymbolAddress((void**)&wa, g_wa);
    cudaGetSymbolAddress((void**)&wp, g_wp);
    cudaGetSymbolAddress((void**)&qh, g_qkvh);
    cudaGetSymbolAddress((void**)&ql, g_qkvl);

    const int flash_smem = (2 * 128 * FP + 8 * 64 * FP) * (int)sizeof(__nv_bfloat16);
    cudaFuncSetAttribute(flash_hmma_kernel,
                         cudaFuncAttributeMaxDynamicSharedMemorySize, flash_smem);

    // 0) preprocessing
    {
        int n = M_TOK * C_EMB;
        split_cat_kernel<<<(n + 255) / 256, 256>>>(x, a1, M_TOK, C_EMB);
    }
    {
        dim3 grid(C3 / 32, C_EMB / 32);
        splitT_cat_kernel<<<grid, dim3(32, 8)>>>(W_attn, wa, C_EMB, C3);
    }
    {
        dim3 grid(C_EMB / 32, C_EMB / 32);
        splitT_cat_kernel<<<grid, dim3(32, 8)>>>(W_proj, wp, C_EMB, C_EMB);
    }

    // 1) QKV GEMM -> bf16 hi/lo qkv
    {
        dim3 grid(C3 / GBN, M_TOK / GBM);
        hmma_gemm_kernel<true><<<grid, 256>>>(
            a1, wa, b_attn, nullptr, qh, ql, M_TOK, C3, K3);
    }

    // 2) Flash attention (HMMA) -> a2 in split-cat layout
    {
        dim3 grid(16, N_HEADS, 4);
        flash_hmma_kernel<<<grid, 256, flash_smem>>>(qh, ql, a2);
    }

    // 3) proj GEMM -> out fp32
    {
        dim3 grid(C_EMB / GBN, M_TOK / GBM);
        hmma_gemm_kernel<false><<<grid, 256>>>(
            a2, wp, b_proj, out, nullptr, nullptr, M_TOK, C_EMB, K3);
    }
}

// round 10
// speedup vs baseline: 2.5471x; 1.0089x over previous
#include <cuda_runtime.h>
#include <cuda_bf16.h>
#include <cstdint>

// Problem constants
#define M_TOK   8192          // B*T = 4*2048
#define C_EMB   1024
#define C3      3072
#define K3      3072          // tripled K for split GEMM (3 * C_EMB)
#define N_HEADS 16
#define D_HEAD  64

// ---------------------------------------------------------------------------
// Scratch (static device globals — allocation-free per harness rules)
// ---------------------------------------------------------------------------
__device__ __nv_bfloat16 g_a1[(size_t)M_TOK * K3];          // 48 MB  x split-cat
__device__ __nv_bfloat16 g_a2[(size_t)M_TOK * K3];          // 48 MB  y split-cat (flash out)
__device__ __nv_bfloat16 g_wa[(size_t)C3 * K3];             // 18 MB  W_attn^T split-cat
__device__ __nv_bfloat16 g_wp[(size_t)C_EMB * K3];          //  6 MB  W_proj^T split-cat
__device__ __nv_bfloat16 g_qkvh[(size_t)M_TOK * C3];        // 48 MB  qkv hi
__device__ __nv_bfloat16 g_qkvl[(size_t)M_TOK * C3];        // 48 MB  qkv lo

// ---------------------------------------------------------------------------
// PTX helpers (baseline sm_103 — NO tcgen05 / 'a'-suffix features)
// ---------------------------------------------------------------------------
__device__ __forceinline__ uint32_t smemu32(const void* p) {
    return (uint32_t)__cvta_generic_to_shared(p);
}

#define CP_ASYNC_16(dst_u32, src_ptr) \
    asm volatile("cp.async.cg.shared.global [%0], [%1], 16;" \
        :: "r"(dst_u32), "l"(src_ptr))
#define CP_COMMIT() asm volatile("cp.async.commit_group;" ::: "memory")
#define CP_WAIT(n)  asm volatile("cp.async.wait_group %0;" :: "n"(n) : "memory")

#define LDMATRIX_X4(r0, r1, r2, r3, addr) \
    asm volatile("ldmatrix.sync.aligned.m8n8.x4.shared.b16 {%0,%1,%2,%3}, [%4];" \
        : "=r"(r0), "=r"(r1), "=r"(r2), "=r"(r3) : "r"(addr))
#define LDMATRIX_X2(r0, r1, addr) \
    asm volatile("ldmatrix.sync.aligned.m8n8.x2.shared.b16 {%0,%1}, [%2];" \
        : "=r"(r0), "=r"(r1) : "r"(addr))
#define LDMATRIX_X2_TRANS(r0, r1, addr) \
    asm volatile("ldmatrix.sync.aligned.m8n8.x2.trans.shared.b16 {%0,%1}, [%2];" \
        : "=r"(r0), "=r"(r1) : "r"(addr))

#define MMA_BF16(d, a, b) \
    asm volatile("mma.sync.aligned.m16n8k16.row.col.f32.bf16.bf16.f32 " \
        "{%0,%1,%2,%3}, {%4,%5,%6,%7}, {%8,%9}, {%0,%1,%2,%3};" \
        : "+f"((d)[0]), "+f"((d)[1]), "+f"((d)[2]), "+f"((d)[3]) \
        : "r"((a)[0]), "r"((a)[1]), "r"((a)[2]), "r"((a)[3]), \
          "r"((b)[0]), "r"((b)[1]))

// split two floats into packed bf16x2 hi and lo
__device__ __forceinline__ void split2(float x, float y, uint32_t& hi, uint32_t& lo) {
    __nv_bfloat16 hx = __float2bfloat16(x), hy = __float2bfloat16(y);
    __nv_bfloat16 lx = __float2bfloat16(x - __bfloat162float(hx));
    __nv_bfloat16 ly = __float2bfloat16(y - __bfloat162float(hy));
    __nv_bfloat162 hp = __nv_bfloat162(hx, hy), lp = __nv_bfloat162(lx, ly);
    hi = *(uint32_t*)&hp;
    lo = *(uint32_t*)&lp;
}

// ---------------------------------------------------------------------------
// split-cat: fp32 [M,K] -> bf16 [M,3K] = [hi | hi | lo]
// ---------------------------------------------------------------------------
__global__ void split_cat_kernel(const float* __restrict__ in,
                                 __nv_bfloat16* __restrict__ outp,
                                 int M, int K)
{
    int i = blockIdx.x * blockDim.x + threadIdx.x;
    if (i < M * K) {
        int m = i / K, k = i % K;
        float v = in[i];
        __nv_bfloat16 h = __float2bfloat16(v);
        __nv_bfloat16 l = __float2bfloat16(v - __bfloat162float(h));
        size_t base = (size_t)m * (3 * K);
        outp[base + k]          = h;
        outp[base + K + k]      = h;
        outp[base + 2 * K + k]  = l;
    }
}

// ---------------------------------------------------------------------------
// transpose-split-cat: fp32 W [K,N] -> bf16 B' [N,3K] = [hi | lo | hi]
// ---------------------------------------------------------------------------
__global__ void splitT_cat_kernel(const float* __restrict__ in,
                                  __nv_bfloat16* __restrict__ outp,
                                  int K, int N)
{
    __shared__ float t[32][33];
    const int n0 = blockIdx.x * 32, k0 = blockIdx.y * 32;
    const int tx = threadIdx.x, ty = threadIdx.y;
#pragma unroll
    for (int i = ty; i < 32; i += 8)
        t[i][tx] = in[(size_t)(k0 + i) * N + n0 + tx];
    __syncthreads();
#pragma unroll
    for (int i = ty; i < 32; i += 8) {
        float v = t[tx][i];
        __nv_bfloat16 h = __float2bfloat16(v);
        __nv_bfloat16 l = __float2bfloat16(v - __bfloat162float(h));
        size_t base = (size_t)(n0 + i) * (3 * K) + k0 + tx;
        outp[base]          = h;
        outp[base + K]      = l;
        outp[base + 2 * K]  = h;
    }
}

// ---------------------------------------------------------------------------
// bf16 mma.sync GEMM: C = A[M,K]@B[N,K]^T + bias
// CTA tile 128x128, BK=32, 4-stage cp.async ring, one __syncthreads per slab.
// BF16OUT=false: write fp32 C.  BF16OUT=true: write bf16 hi/lo (Ch, Cl).
// ---------------------------------------------------------------------------
#define GBM 128
#define GBN 128
#define GBK 32
#define LDSD 40
#define STG 4
#define GEMM_SMEM (STG * (GBM + GBN) * LDSD * 2)   // 81920 bytes

template<bool BF16OUT>
__global__ __launch_bounds__(256) void hmma_gemm_kernel(
    const __nv_bfloat16* __restrict__ A,
    const __nv_bfloat16* __restrict__ B,
    const float* __restrict__ bias, float* __restrict__ C,
    __nv_bfloat16* __restrict__ Ch, __nv_bfloat16* __restrict__ Cl,
    int M, int N, int K)
{
    extern __shared__ __nv_bfloat16 gsm[];
    __nv_bfloat16* Asm = gsm;                         // STG stages of GBM*LDSD
    __nv_bfloat16* Bsm = gsm + STG * GBM * LDSD;      // STG stages of GBN*LDSD

    const int tid  = threadIdx.x;
    const int wid  = tid >> 5, lane = tid & 31;
    const int bm   = blockIdx.y * GBM, bn = blockIdx.x * GBN;
    const int wm   = (wid & 1) * 64;
    const int wn   = (wid >> 1) * 32;

    float acc[4][4][4];
#pragma unroll
    for (int mi = 0; mi < 4; mi++)
#pragma unroll
        for (int ni = 0; ni < 4; ni++)
#pragma unroll
            for (int r = 0; r < 4; r++) acc[mi][ni][r] = 0.f;

    const __nv_bfloat16* gA = A + (size_t)bm * K;
    const __nv_bfloat16* gB = B + (size_t)bn * K;

    const int lr0 = tid >> 2;             // 0..63
    const int lc  = (tid & 3) * 8;        // k-col (bf16 elems)

    auto load_slab = [&](int st, int k0) {
        __nv_bfloat16* as = Asm + st * GBM * LDSD;
        __nv_bfloat16* bs = Bsm + st * GBN * LDSD;
#pragma unroll
        for (int half = 0; half < 2; half++) {
            const int r = lr0 + half * 64;
            const size_t go = (size_t)r * K + k0 + lc;
            CP_ASYNC_16(smemu32(&as[r * LDSD + lc]), gA + go);
            CP_ASYNC_16(smemu32(&bs[r * LDSD + lc]), gB + go);
        }
    };

    const int NS = K / GBK;
    // prologue: stages 0..STG-2
#pragma unroll
    for (int p = 0; p < STG - 1; p++) {
        load_slab(p, p * GBK);
        CP_COMMIT();
    }

    for (int s = 0; s < NS; s++) {
        CP_WAIT(STG - 2);       // stage s resident (always-commit accounting)
        __syncthreads();        // all warps past compute(s-1); stage s visible

        // issue load for stage s+STG-1 into buffer (s-1)%STG (consumed at s-1)
        if (s + STG - 1 < NS)
            load_slab((s + STG - 1) % STG, (s + STG - 1) * GBK);
        CP_COMMIT();            // empty group if no load: keeps accounting exact

        const int buf = s % STG;
        const __nv_bfloat16* as = Asm + buf * GBM * LDSD;
        const __nv_bfloat16* bs = Bsm + buf * GBN * LDSD;

#pragma unroll
        for (int kk = 0; kk < GBK; kk += 16) {
            uint32_t af[4][4], bf[4][2];
#pragma unroll
            for (int mi = 0; mi < 4; mi++) {
                const int row = wm + mi * 16 + (lane & 15);
                const int col = kk + (lane >> 4) * 8;
                LDMATRIX_X4(af[mi][0], af[mi][1], af[mi][2], af[mi][3],
                            smemu32(&as[row * LDSD + col]));
            }
#pragma unroll
            for (int ni = 0; ni < 4; ni++) {
                const int nrow = wn + ni * 8 + (lane & 7);
                const int col  = kk + ((lane >> 3) & 1) * 8;
                LDMATRIX_X2(bf[ni][0], bf[ni][1],
                            smemu32(&bs[nrow * LDSD + col]));
            }
#pragma unroll
            for (int mi = 0; mi < 4; mi++)
#pragma unroll
                for (int ni = 0; ni < 4; ni++)
                    MMA_BF16(acc[mi][ni], af[mi], bf[ni]);
        }
    }

    const int gq = lane >> 2;
    const int qp = (lane & 3) * 2;
#pragma unroll
    for (int mi = 0; mi < 4; mi++) {
        const int r0 = bm + wm + mi * 16 + gq;
#pragma unroll
        for (int ni = 0; ni < 4; ni++) {
            const int col = bn + wn + ni * 8 + qp;
            const float bx = __ldg(&bias[col]), by = __ldg(&bias[col + 1]);
            float v0 = acc[mi][ni][0] + bx, v1 = acc[mi][ni][1] + by;
            float v2 = acc[mi][ni][2] + bx, v3 = acc[mi][ni][3] + by;
            if (!BF16OUT) {
                *(float2*)&C[(size_t)r0 * N + col]       = make_float2(v0, v1);
                *(float2*)&C[(size_t)(r0 + 8) * N + col] = make_float2(v2, v3);
            } else {
                uint32_t h0, l0, h1, l1;
                split2(v0, v1, h0, l0);
                split2(v2, v3, h1, l1);
                *(uint32_t*)&Ch[(size_t)r0 * N + col]       = h0;
                *(uint32_t*)&Cl[(size_t)r0 * N + col]       = l0;
                *(uint32_t*)&Ch[(size_t)(r0 + 8) * N + col] = h1;
                *(uint32_t*)&Cl[(size_t)(r0 + 8) * N + col] = l1;
            }
        }
    }
}

// ---------------------------------------------------------------------------
// Flash attention, HMMA bf16 split — unchanged from R7 (passing, ~370us).
// ---------------------------------------------------------------------------
#define FP 72   // padded smem row stride (bf16) — conflict-free ldmatrix

__global__ __launch_bounds__(256) void flash_hmma_kernel(
    const __nv_bfloat16* __restrict__ qkh,
    const __nv_bfloat16* __restrict__ qkl,
    __nv_bfloat16* __restrict__ ycat)
{
    extern __shared__ __nv_bfloat16 sm[];
    __nv_bfloat16* sQh = sm;                     // 128*FP
    __nv_bfloat16* sQl = sQh + 128 * FP;
    __nv_bfloat16* sKh = sQl + 128 * FP;         // 2 stages of 64*FP
    __nv_bfloat16* sKl = sKh + 2 * 64 * FP;
    __nv_bfloat16* sVh = sKl + 2 * 64 * FP;
    __nv_bfloat16* sVl = sVh + 2 * 64 * FP;

    const int tid = threadIdx.x, wid = tid >> 5, lane = tid & 31;
    const int qt = (int)gridDim.x - 1 - (int)blockIdx.x;   // heavy tiles first
    const int h = blockIdx.y, b = blockIdx.z;
    const int q0 = qt * 128;
    const size_t tokQ = (size_t)b * 2048 + q0;
    const int colQ = h * 64;

    // Q tile (hi+lo) via cp.async
    for (int i = tid; i < 1024; i += 256) {
        const int r = i >> 3, c = (i & 7) * 8;
        const size_t g = (tokQ + r) * C3 + colQ + c;
        CP_ASYNC_16(smemu32(&sQh[r * FP + c]), qkh + g);
        CP_ASYNC_16(smemu32(&sQl[r * FP + c]), qkl + g);
    }
    auto load_kv = [&](int st, int k0) {
        __nv_bfloat16* kh = sKh + st * 64 * FP;
        __nv_bfloat16* kl = sKl + st * 64 * FP;
        __nv_bfloat16* vh = sVh + st * 64 * FP;
        __nv_bfloat16* vl = sVl + st * 64 * FP;
        for (int i = tid; i < 512; i += 256) {
            const int r = i >> 3, c = (i & 7) * 8;
            const size_t gk = ((size_t)b * 2048 + k0 + r) * C3 + C_EMB + colQ + c;
            const size_t gv = gk + C_EMB;
            CP_ASYNC_16(smemu32(&kh[r * FP + c]), qkh + gk);
            CP_ASYNC_16(smemu32(&kl[r * FP + c]), qkl + gk);
            CP_ASYNC_16(smemu32(&vh[r * FP + c]), qkh + gv);
            CP_ASYNC_16(smemu32(&vl[r * FP + c]), qkl + gv);
        }
    };
    load_kv(0, 0);
    CP_COMMIT();

    float o[8][4];
#pragma unroll
    for (int dt = 0; dt < 8; dt++)
#pragma unroll
        for (int e = 0; e < 4; e++) o[dt][e] = 0.f;
    float m0 = -1e30f, m1 = -1e30f, l0 = 0.f, l1 = 0.f;
    uint32_t qfh[4][4], qfl[4][4];

    const int gq = lane >> 2, qp2 = (lane & 3) * 2;
    const int row0 = q0 + wid * 16 + gq, row1 = row0 + 8;
    const int ktiles = 2 * qt + 2;

    for (int kt = 0; kt < ktiles; kt++) {
        if (kt + 1 < ktiles) {
            load_kv((kt + 1) & 1, (kt + 1) * 64);
            CP_COMMIT();
            CP_WAIT(1);
        } else {
            CP_WAIT(0);
        }
        __syncthreads();

        if (kt == 0) {
#pragma unroll
            for (int ks = 0; ks < 4; ks++) {
                const int qrow = wid * 16 + (lane & 15);
                const int qcol = ks * 16 + (lane >> 4) * 8;
                LDMATRIX_X4(qfh[ks][0], qfh[ks][1], qfh[ks][2], qfh[ks][3],
                            smemu32(&sQh[qrow * FP + qcol]));
                LDMATRIX_X4(qfl[ks][0], qfl[ks][1], qfl[ks][2], qfl[ks][3],
                            smemu32(&sQl[qrow * FP + qcol]));
            }
        }

        const int st = kt & 1, k0 = kt * 64;
        const __nv_bfloat16* kh = sKh + st * 64 * FP;
        const __nv_bfloat16* kl = sKl + st * 64 * FP;
        const __nv_bfloat16* vh = sVh + st * 64 * FP;
        const __nv_bfloat16* vl = sVl + st * 64 * FP;

        float s[8][4];
#pragma unroll
        for (int nt = 0; nt < 8; nt++)
#pragma unroll
            for (int e = 0; e < 4; e++) s[nt][e] = 0.f;

#pragma unroll
        for (int ks = 0; ks < 4; ks++) {
#pragma unroll
            for (int nt = 0; nt < 8; nt++) {
                uint32_t bh[2], bl[2];
                const int krow = nt * 8 + (lane & 7);
                const int kcol = ks * 16 + ((lane >> 3) & 1) * 8;
                LDMATRIX_X2(bh[0], bh[1], smemu32(&kh[krow * FP + kcol]));
                LDMATRIX_X2(bl[0], bl[1], smemu32(&kl[krow * FP + kcol]));
                MMA_BF16(s[nt], qfh[ks], bh);
                MMA_BF16(s[nt], qfl[ks], bh);
                MMA_BF16(s[nt], qfh[ks], bl);
            }
        }

        const bool domask = (kt >= 2 * qt);
        float t0 = -1e30f, t1 = -1e30f;
#pragma unroll
        for (int nt = 0; nt < 8; nt++) {
#pragma unroll
            for (int e = 0; e < 4; e++) s[nt][e] *= 0.125f;
            if (domask) {
                const int c0 = k0 + nt * 8 + qp2;
                if (c0 > row0)     s[nt][0] = -1e30f;
                if (c0 + 1 > row0) s[nt][1] = -1e30f;
                if (c0 > row1)     s[nt][2] = -1e30f;
                if (c0 + 1 > row1) s[nt][3] = -1e30f;
            }
            t0 = fmaxf(t0, fmaxf(s[nt][0], s[nt][1]));
            t1 = fmaxf(t1, fmaxf(s[nt][2], s[nt][3]));
        }
        t0 = fmaxf(t0, __shfl_xor_sync(0xFFFFFFFFu, t0, 1));
        t0 = fmaxf(t0, __shfl_xor_sync(0xFFFFFFFFu, t0, 2));
        t1 = fmaxf(t1, __shfl_xor_sync(0xFFFFFFFFu, t1, 1));
        t1 = fmaxf(t1, __shfl_xor_sync(0xFFFFFFFFu, t1, 2));

        const float mn0 = fmaxf(m0, t0), mn1 = fmaxf(m1, t1);
        const float cr0 = __expf(m0 - mn0), cr1 = __expf(m1 - mn1);
        m0 = mn0; m1 = mn1;

        float sum0 = 0.f, sum1 = 0.f;
#pragma unroll
        for (int nt = 0; nt < 8; nt++) {
            s[nt][0] = __expf(s[nt][0] - m0);
            s[nt][1] = __expf(s[nt][1] - m0);
            s[nt][2] = __expf(s[nt][2] - m1);
            s[nt][3] = __expf(s[nt][3] - m1);
            sum0 += s[nt][0] + s[nt][1];
            sum1 += s[nt][2] + s[nt][3];
        }
        sum0 += __shfl_xor_sync(0xFFFFFFFFu, sum0, 1);
        sum0 += __shfl_xor_sync(0xFFFFFFFFu, sum0, 2);
        sum1 += __shfl_xor_sync(0xFFFFFFFFu, sum1, 1);
        sum1 += __shfl_xor_sync(0xFFFFFFFFu, sum1, 2);
        l0 = l0 * cr0 + sum0;
        l1 = l1 * cr1 + sum1;

#pragma unroll
        for (int dt = 0; dt < 8; dt++) {
            o[dt][0] *= cr0; o[dt][1] *= cr0;
            o[dt][2] *= cr1; o[dt][3] *= cr1;
        }

#pragma unroll
        for (int t = 0; t < 4; t++) {
            uint32_t ah[4], al[4];
            split2(s[2 * t][0],     s[2 * t][1],     ah[0], al[0]);
            split2(s[2 * t][2],     s[2 * t][3],     ah[1], al[1]);
            split2(s[2 * t + 1][0], s[2 * t + 1][1], ah[2], al[2]);
            split2(s[2 * t + 1][2], s[2 * t + 1][3], ah[3], al[3]);
#pragma unroll
            for (int dt = 0; dt < 8; dt++) {
                uint32_t bvh[2], bvl[2];
                const int vrow = t * 16 + (lane & 15);
                LDMATRIX_X2_TRANS(bvh[0], bvh[1], smemu32(&vh[vrow * FP + dt * 8]));
                LDMATRIX_X2_TRANS(bvl[0], bvl[1], smemu32(&vl[vrow * FP + dt * 8]));
                MMA_BF16(o[dt], ah, bvh);
                MMA_BF16(o[dt], al, bvh);
                MMA_BF16(o[dt], ah, bvl);
            }
        }
        __syncthreads();
    }

    const float inv0 = 1.f / l0, inv1 = 1.f / l1;
    const size_t tok0 = tokQ + wid * 16 + gq;
    const size_t base0 = tok0 * K3 + colQ;
    const size_t base1 = (tok0 + 8) * K3 + colQ;
#pragma unroll
    for (int dt = 0; dt < 8; dt++) {
        const int c = dt * 8 + qp2;
        uint32_t h0, lo0, h1, lo1;
        split2(o[dt][0] * inv0, o[dt][1] * inv0, h0, lo0);
        split2(o[dt][2] * inv1, o[dt][3] * inv1, h1, lo1);
        *(uint32_t*)&ycat[base0 + c]              = h0;
        *(uint32_t*)&ycat[base0 + C_EMB + c]      = h0;
        *(uint32_t*)&ycat[base0 + 2 * C_EMB + c]  = lo0;
        *(uint32_t*)&ycat[base1 + c]              = h1;
        *(uint32_t*)&ycat[base1 + C_EMB + c]      = h1;
        *(uint32_t*)&ycat[base1 + 2 * C_EMB + c]  = lo1;
    }
}

// ---------------------------------------------------------------------------
// Launch
// ---------------------------------------------------------------------------
extern "C" void kernel_launch(void* const* d_in, const int* in_sizes, int n_in,
                              void* d_out, int out_size)
{
    const float* x      = (const float*)d_in[0];
    const float* W_attn = (const float*)d_in[1];
    const float* b_attn = (const float*)d_in[2];
    const float* W_proj = (const float*)d_in[3];
    const float* b_proj = (const float*)d_in[4];
    float* out = (float*)d_out;

    __nv_bfloat16 *a1, *a2, *wa, *wp, *qh, *ql;
    cudaGetSymbolAddress((void**)&a1, g_a1);
    cudaGetSymbolAddress((void**)&a2, g_a2);
    cudaGetSymbolAddress((void**)&wa, g_wa);
    cudaGetSymbolAddress((void**)&wp, g_wp);
    cudaGetSymbolAddress((void**)&qh, g_qkvh);
    cudaGetSymbolAddress((void**)&ql, g_qkvl);

    const int flash_smem = (2 * 128 * FP + 8 * 64 * FP) * (int)sizeof(__nv_bfloat16);
    cudaFuncSetAttribute(flash_hmma_kernel,
                         cudaFuncAttributeMaxDynamicSharedMemorySize, flash_smem);
    cudaFuncSetAttribute(hmma_gemm_kernel<true>,
                         cudaFuncAttributeMaxDynamicSharedMemorySize, GEMM_SMEM);
    cudaFuncSetAttribute(hmma_gemm_kernel<false>,
                         cudaFuncAttributeMaxDynamicSharedMemorySize, GEMM_SMEM);

    // 0) preprocessing
    {
        int n = M_TOK * C_EMB;
        split_cat_kernel<<<(n + 255) / 256, 256>>>(x, a1, M_TOK, C_EMB);
    }
    {
        dim3 grid(C3 / 32, C_EMB / 32);
        splitT_cat_kernel<<<grid, dim3(32, 8)>>>(W_attn, wa, C_EMB, C3);
    }
    {
        dim3 grid(C_EMB / 32, C_EMB / 32);
        splitT_cat_kernel<<<grid, dim3(32, 8)>>>(W_proj, wp, C_EMB, C_EMB);
    }

    // 1) QKV GEMM -> bf16 hi/lo qkv
    {
        dim3 grid(C3 / GBN, M_TOK / GBM);
        hmma_gemm_kernel<true><<<grid, 256, GEMM_SMEM>>>(
            a1, wa, b_attn, nullptr, qh, ql, M_TOK, C3, K3);
    }

    // 2) Flash attention (HMMA) -> a2 in split-cat layout
    {
        dim3 grid(16, N_HEADS, 4);
        flash_hmma_kernel<<<grid, 256, flash_smem>>>(qh, ql, a2);
    }

    // 3) proj GEMM -> out fp32
    {
        dim3 grid(C_EMB / GBN, M_TOK / GBM);
        hmma_gemm_kernel<false><<<grid, 256, GEMM_SMEM>>>(
            a2, wp, b_proj, out, nullptr, nullptr, M_TOK, C_EMB, K3);
    }
}

// round 16
// speedup vs baseline: 2.7082x; 1.0632x over previous
#include <cuda_runtime.h>
#include <cuda_bf16.h>
#include <cstdint>

// Problem constants
#define M_TOK   8192          // B*T = 4*2048
#define C_EMB   1024
#define C3      3072
#define K3      3072          // tripled K for split GEMM (3 * C_EMB)
#define N_HEADS 16
#define D_HEAD  64

// ---------------------------------------------------------------------------
// Scratch (static device globals — allocation-free per harness rules)
// ---------------------------------------------------------------------------
__device__ __nv_bfloat16 g_a1[(size_t)M_TOK * K3];          // 48 MB  x split-cat
__device__ __nv_bfloat16 g_a2[(size_t)M_TOK * K3];          // 48 MB  y split-cat (flash out)
__device__ __nv_bfloat16 g_wa[(size_t)C3 * K3];             // 18 MB  W_attn^T split-cat
__device__ __nv_bfloat16 g_wp[(size_t)C_EMB * K3];          //  6 MB  W_proj^T split-cat
__device__ __nv_bfloat16 g_qkvh[(size_t)M_TOK * C3];        // 48 MB  qkv hi
__device__ __nv_bfloat16 g_qkvl[(size_t)M_TOK * C3];        // 48 MB  qkv lo

// ---------------------------------------------------------------------------
// PTX helpers (baseline sm_103 — NO tcgen05 / 'a'-suffix features)
// ---------------------------------------------------------------------------
__device__ __forceinline__ uint32_t smemu32(const void* p) {
    return (uint32_t)__cvta_generic_to_shared(p);
}

#define CP_ASYNC_16(dst_u32, src_ptr) \
    asm volatile("cp.async.cg.shared.global [%0], [%1], 16;" \
        :: "r"(dst_u32), "l"(src_ptr))
#define CP_COMMIT() asm volatile("cp.async.commit_group;" ::: "memory")
#define CP_WAIT(n)  asm volatile("cp.async.wait_group %0;" :: "n"(n) : "memory")

#define LDMATRIX_X4(r0, r1, r2, r3, addr) \
    asm volatile("ldmatrix.sync.aligned.m8n8.x4.shared.b16 {%0,%1,%2,%3}, [%4];" \
        : "=r"(r0), "=r"(r1), "=r"(r2), "=r"(r3) : "r"(addr))
#define LDMATRIX_X2(r0, r1, addr) \
    asm volatile("ldmatrix.sync.aligned.m8n8.x2.shared.b16 {%0,%1}, [%2];" \
        : "=r"(r0), "=r"(r1) : "r"(addr))
#define LDMATRIX_X2_TRANS(r0, r1, addr) \
    asm volatile("ldmatrix.sync.aligned.m8n8.x2.trans.shared.b16 {%0,%1}, [%2];" \
        : "=r"(r0), "=r"(r1) : "r"(addr))

#define MMA_BF16(d, a, b) \
    asm volatile("mma.sync.aligned.m16n8k16.row.col.f32.bf16.bf16.f32 " \
        "{%0,%1,%2,%3}, {%4,%5,%6,%7}, {%8,%9}, {%0,%1,%2,%3};" \
        : "+f"((d)[0]), "+f"((d)[1]), "+f"((d)[2]), "+f"((d)[3]) \
        : "r"((a)[0]), "r"((a)[1]), "r"((a)[2]), "r"((a)[3]), \
          "r"((b)[0]), "r"((b)[1]))

// split two floats into packed bf16x2 hi and lo
__device__ __forceinline__ void split2(float x, float y, uint32_t& hi, uint32_t& lo) {
    __nv_bfloat16 hx = __float2bfloat16(x), hy = __float2bfloat16(y);
    __nv_bfloat16 lx = __float2bfloat16(x - __bfloat162float(hx));
    __nv_bfloat16 ly = __float2bfloat16(y - __bfloat162float(hy));
    __nv_bfloat162 hp = __nv_bfloat162(hx, hy), lp = __nv_bfloat162(lx, ly);
    hi = *(uint32_t*)&hp;
    lo = *(uint32_t*)&lp;
}

// ---------------------------------------------------------------------------
// split-cat: fp32 [M,K] -> bf16 [M,3K] = [hi | hi | lo]
// ---------------------------------------------------------------------------
__global__ void split_cat_kernel(const float* __restrict__ in,
                                 __nv_bfloat16* __restrict__ outp,
                                 int M, int K)
{
    int i = blockIdx.x * blockDim.x + threadIdx.x;
    if (i < M * K) {
        int m = i / K, k = i % K;
        float v = in[i];
        __nv_bfloat16 h = __float2bfloat16(v);
        __nv_bfloat16 l = __float2bfloat16(v - __bfloat162float(h));
        size_t base = (size_t)m * (3 * K);
        outp[base + k]          = h;
        outp[base + K + k]      = h;
        outp[base + 2 * K + k]  = l;
    }
}

// ---------------------------------------------------------------------------
// transpose-split-cat: fp32 W [K,N] -> bf16 B' [N,3K] = [hi | lo | hi]
// ---------------------------------------------------------------------------
__global__ void splitT_cat_kernel(const float* __restrict__ in,
                                  __nv_bfloat16* __restrict__ outp,
                                  int K, int N)
{
    __shared__ float t[32][33];
    const int n0 = blockIdx.x * 32, k0 = blockIdx.y * 32;
    const int tx = threadIdx.x, ty = threadIdx.y;
#pragma unroll
    for (int i = ty; i < 32; i += 8)
        t[i][tx] = in[(size_t)(k0 + i) * N + n0 + tx];
    __syncthreads();
#pragma unroll
    for (int i = ty; i < 32; i += 8) {
        float v = t[tx][i];
        __nv_bfloat16 h = __float2bfloat16(v);
        __nv_bfloat16 l = __float2bfloat16(v - __bfloat162float(h));
        size_t base = (size_t)(n0 + i) * (3 * K) + k0 + tx;
        outp[base]          = h;
        outp[base + K]      = l;
        outp[base + 2 * K]  = h;
    }
}

// ---------------------------------------------------------------------------
// bf16 mma.sync GEMM: C = A[M,K]@B[N,K]^T + bias
// CTA tile 128x64 (8 warps 4x2, warp tile 32x32), BK=32, 4-stage cp.async
// ring, __launch_bounds__(256,3) for 3 CTAs/SM (occupancy play vs R10).
// BF16OUT=false: write fp32 C.  BF16OUT=true: write bf16 hi/lo (Ch, Cl).
// ---------------------------------------------------------------------------
#define GBM 128
#define GBN 64
#define GBK 32
#define LDSD 40
#define STG 4
#define GEMM_SMEM (STG * (GBM + GBN) * LDSD * 2)   // 61440 bytes

template<bool BF16OUT>
__global__ __launch_bounds__(256, 3) void hmma_gemm_kernel(
    const __nv_bfloat16* __restrict__ A,
    const __nv_bfloat16* __restrict__ B,
    const float* __restrict__ bias, float* __restrict__ C,
    __nv_bfloat16* __restrict__ Ch, __nv_bfloat16* __restrict__ Cl,
    int M, int N, int K)
{
    extern __shared__ __nv_bfloat16 gsm[];
    __nv_bfloat16* Asm = gsm;                         // STG stages of GBM*LDSD
    __nv_bfloat16* Bsm = gsm + STG * GBM * LDSD;      // STG stages of GBN*LDSD

    const int tid  = threadIdx.x;
    const int wid  = tid >> 5, lane = tid & 31;
    const int bm   = blockIdx.y * GBM, bn = blockIdx.x * GBN;
    const int wm   = (wid & 3) * 32;    // 4 warps in M
    const int wn   = (wid >> 2) * 32;   // 2 warps in N

    float acc[2][4][4];
#pragma unroll
    for (int mi = 0; mi < 2; mi++)
#pragma unroll
        for (int ni = 0; ni < 4; ni++)
#pragma unroll
            for (int r = 0; r < 4; r++) acc[mi][ni][r] = 0.f;

    const __nv_bfloat16* gA = A + (size_t)bm * K;
    const __nv_bfloat16* gB = B + (size_t)bn * K;

    const int lr0 = tid >> 2;             // 0..63
    const int lc  = (tid & 3) * 8;        // k-col (bf16 elems)

    auto load_slab = [&](int st, int k0) {
        __nv_bfloat16* as = Asm + st * GBM * LDSD;
        __nv_bfloat16* bs = Bsm + st * GBN * LDSD;
        // A: 128 rows (2 halves), B: 64 rows (1 pass). 3 cp.async per thread.
#pragma unroll
        for (int half = 0; half < 2; half++) {
            const int r = lr0 + half * 64;
            CP_ASYNC_16(smemu32(&as[r * LDSD + lc]), gA + (size_t)r * K + k0 + lc);
        }
        CP_ASYNC_16(smemu32(&bs[lr0 * LDSD + lc]), gB + (size_t)lr0 * K + k0 + lc);
    };

    const int NS = K / GBK;
    // prologue: stages 0..STG-2
#pragma unroll
    for (int p = 0; p < STG - 1; p++) {
        load_slab(p, p * GBK);
        CP_COMMIT();
    }

    // B x4 fragment addressing: m = lane>>3 selects (n-subtile, k-half)
    const int bq_row = ((lane >> 4) & 1) * 8 + (lane & 7);  // (m>>1)*8 + lane%8
    const int bq_kh  = ((lane >> 3) & 1) * 8;               // (m&1)*8

    for (int s = 0; s < NS; s++) {
        CP_WAIT(STG - 2);       // stage s resident (always-commit accounting)
        __syncthreads();        // all warps past compute(s-1); stage s visible

        if (s + STG - 1 < NS)
            load_slab((s + STG - 1) % STG, (s + STG - 1) * GBK);
        CP_COMMIT();            // empty group if no load: keeps accounting exact

        const int buf = s % STG;
        const __nv_bfloat16* as = Asm + buf * GBM * LDSD;
        const __nv_bfloat16* bs = Bsm + buf * GBN * LDSD;

#pragma unroll
        for (int kk = 0; kk < GBK; kk += 16) {
            uint32_t af[2][4], bf[4][2];
#pragma unroll
            for (int mi = 0; mi < 2; mi++) {
                const int row = wm + mi * 16 + (lane & 15);
                const int col = kk + (lane >> 4) * 8;
                LDMATRIX_X4(af[mi][0], af[mi][1], af[mi][2], af[mi][3],
                            smemu32(&as[row * LDSD + col]));
            }
            // B: one x4 covers two n8-tiles (both k-halves)
#pragma unroll
            for (int np = 0; np < 2; np++) {
                const int nrow = wn + np * 16 + bq_row;
                const int col  = kk + bq_kh;
                LDMATRIX_X4(bf[2 * np][0], bf[2 * np][1],
                            bf[2 * np + 1][0], bf[2 * np + 1][1],
                            smemu32(&bs[nrow * LDSD + col]));
            }
#pragma unroll
            for (int mi = 0; mi < 2; mi++)
#pragma unroll
                for (int ni = 0; ni < 4; ni++)
                    MMA_BF16(acc[mi][ni], af[mi], bf[ni]);
        }
    }

    const int gq = lane >> 2;
    const int qp = (lane & 3) * 2;
#pragma unroll
    for (int mi = 0; mi < 2; mi++) {
        const int r0 = bm + wm + mi * 16 + gq;
#pragma unroll
        for (int ni = 0; ni < 4; ni++) {
            const int col = bn + wn + ni * 8 + qp;
            const float bx = __ldg(&bias[col]), by = __ldg(&bias[col + 1]);
            float v0 = acc[mi][ni][0] + bx, v1 = acc[mi][ni][1] + by;
            float v2 = acc[mi][ni][2] + bx, v3 = acc[mi][ni][3] + by;
            if (!BF16OUT) {
                *(float2*)&C[(size_t)r0 * N + col]       = make_float2(v0, v1);
                *(float2*)&C[(size_t)(r0 + 8) * N + col] = make_float2(v2, v3);
            } else {
                uint32_t h0, l0, h1, l1;
                split2(v0, v1, h0, l0);
                split2(v2, v3, h1, l1);
                *(uint32_t*)&Ch[(size_t)r0 * N + col]       = h0;
                *(uint32_t*)&Cl[(size_t)r0 * N + col]       = l0;
                *(uint32_t*)&Ch[(size_t)(r0 + 8) * N + col] = h1;
                *(uint32_t*)&Cl[(size_t)(r0 + 8) * N + col] = l1;
            }
        }
    }
}

// ---------------------------------------------------------------------------
// Flash attention, HMMA bf16 split — unchanged from R7/R10 (passing, ~370us).
// ---------------------------------------------------------------------------
#define FP 72   // padded smem row stride (bf16) — conflict-free ldmatrix

__global__ __launch_bounds__(256) void flash_hmma_kernel(
    const __nv_bfloat16* __restrict__ qkh,
    const __nv_bfloat16* __restrict__ qkl,
    __nv_bfloat16* __restrict__ ycat)
{
    extern __shared__ __nv_bfloat16 sm[];
    __nv_bfloat16* sQh = sm;                     // 128*FP
    __nv_bfloat16* sQl = sQh + 128 * FP;
    __nv_bfloat16* sKh = sQl + 128 * FP;         // 2 stages of 64*FP
    __nv_bfloat16* sKl = sKh + 2 * 64 * FP;
    __nv_bfloat16* sVh = sKl + 2 * 64 * FP;
    __nv_bfloat16* sVl = sVh + 2 * 64 * FP;

    const int tid = threadIdx.x, wid = tid >> 5, lane = tid & 31;
    const int qt = (int)gridDim.x - 1 - (int)blockIdx.x;   // heavy tiles first
    const int h = blockIdx.y, b = blockIdx.z;
    const int q0 = qt * 128;
    const size_t tokQ = (size_t)b * 2048 + q0;
    const int colQ = h * 64;

    // Q tile (hi+lo) via cp.async
    for (int i = tid; i < 1024; i += 256) {
        const int r = i >> 3, c = (i & 7) * 8;
        const size_t g = (tokQ + r) * C3 + colQ + c;
        CP_ASYNC_16(smemu32(&sQh[r * FP + c]), qkh + g);
        CP_ASYNC_16(smemu32(&sQl[r * FP + c]), qkl + g);
    }
    auto load_kv = [&](int st, int k0) {
        __nv_bfloat16* kh = sKh + st * 64 * FP;
        __nv_bfloat16* kl = sKl + st * 64 * FP;
        __nv_bfloat16* vh = sVh + st * 64 * FP;
        __nv_bfloat16* vl = sVl + st * 64 * FP;
        for (int i = tid; i < 512; i += 256) {
            const int r = i >> 3, c = (i & 7) * 8;
            const size_t gk = ((size_t)b * 2048 + k0 + r) * C3 + C_EMB + colQ + c;
            const size_t gv = gk + C_EMB;
            CP_ASYNC_16(smemu32(&kh[r * FP + c]), qkh + gk);
            CP_ASYNC_16(smemu32(&kl[r * FP + c]), qkl + gk);
            CP_ASYNC_16(smemu32(&vh[r * FP + c]), qkh + gv);
            CP_ASYNC_16(smemu32(&vl[r * FP + c]), qkl + gv);
        }
    };
    load_kv(0, 0);
    CP_COMMIT();

    float o[8][4];
#pragma unroll
    for (int dt = 0; dt < 8; dt++)
#pragma unroll
        for (int e = 0; e < 4; e++) o[dt][e] = 0.f;
    float m0 = -1e30f, m1 = -1e30f, l0 = 0.f, l1 = 0.f;
    uint32_t qfh[4][4], qfl[4][4];

    const int gq = lane >> 2, qp2 = (lane & 3) * 2;
    const int row0 = q0 + wid * 16 + gq, row1 = row0 + 8;
    const int ktiles = 2 * qt + 2;

    for (int kt = 0; kt < ktiles; kt++) {
        if (kt + 1 < ktiles) {
            load_kv((kt + 1) & 1, (kt + 1) * 64);
            CP_COMMIT();
            CP_WAIT(1);
        } else {
            CP_WAIT(0);
        }
        __syncthreads();

        if (kt == 0) {
#pragma unroll
            for (int ks = 0; ks < 4; ks++) {
                const int qrow = wid * 16 + (lane & 15);
                const int qcol = ks * 16 + (lane >> 4) * 8;
                LDMATRIX_X4(qfh[ks][0], qfh[ks][1], qfh[ks][2], qfh[ks][3],
                            smemu32(&sQh[qrow * FP + qcol]));
                LDMATRIX_X4(qfl[ks][0], qfl[ks][1], qfl[ks][2], qfl[ks][3],
                            smemu32(&sQl[qrow * FP + qcol]));
            }
        }

        const int st = kt & 1, k0 = kt * 64;
        const __nv_bfloat16* kh = sKh + st * 64 * FP;
        const __nv_bfloat16* kl = sKl + st * 64 * FP;
        const __nv_bfloat16* vh = sVh + st * 64 * FP;
        const __nv_bfloat16* vl = sVl + st * 64 * FP;

        float s[8][4];
#pragma unroll
        for (int nt = 0; nt < 8; nt++)
#pragma unroll
            for (int e = 0; e < 4; e++) s[nt][e] = 0.f;

#pragma unroll
        for (int ks = 0; ks < 4; ks++) {
#pragma unroll
            for (int nt = 0; nt < 8; nt++) {
                uint32_t bh[2], bl[2];
                const int krow = nt * 8 + (lane & 7);
                const int kcol = ks * 16 + ((lane >> 3) & 1) * 8;
                LDMATRIX_X2(bh[0], bh[1], smemu32(&kh[krow * FP + kcol]));
                LDMATRIX_X2(bl[0], bl[1], smemu32(&kl[krow * FP + kcol]));
                MMA_BF16(s[nt], qfh[ks], bh);
                MMA_BF16(s[nt], qfl[ks], bh);
                MMA_BF16(s[nt], qfh[ks], bl);
            }
        }

        const bool domask = (kt >= 2 * qt);
        float t0 = -1e30f, t1 = -1e30f;
#pragma unroll
        for (int nt = 0; nt < 8; nt++) {
#pragma unroll
            for (int e = 0; e < 4; e++) s[nt][e] *= 0.125f;
            if (domask) {
                const int c0 = k0 + nt * 8 + qp2;
                if (c0 > row0)     s[nt][0] = -1e30f;
                if (c0 + 1 > row0) s[nt][1] = -1e30f;
                if (c0 > row1)     s[nt][2] = -1e30f;
                if (c0 + 1 > row1) s[nt][3] = -1e30f;
            }
            t0 = fmaxf(t0, fmaxf(s[nt][0], s[nt][1]));
            t1 = fmaxf(t1, fmaxf(s[nt][2], s[nt][3]));
        }
        t0 = fmaxf(t0, __shfl_xor_sync(0xFFFFFFFFu, t0, 1));
        t0 = fmaxf(t0, __shfl_xor_sync(0xFFFFFFFFu, t0, 2));
        t1 = fmaxf(t1, __shfl_xor_sync(0xFFFFFFFFu, t1, 1));
        t1 = fmaxf(t1, __shfl_xor_sync(0xFFFFFFFFu, t1, 2));

        const float mn0 = fmaxf(m0, t0), mn1 = fmaxf(m1, t1);
        const float cr0 = __expf(m0 - mn0), cr1 = __expf(m1 - mn1);
        m0 = mn0; m1 = mn1;

        float sum0 = 0.f, sum1 = 0.f;
#pragma unroll
        for (int nt = 0; nt < 8; nt++) {
            s[nt][0] = __expf(s[nt][0] - m0);
            s[nt][1] = __expf(s[nt][1] - m0);
            s[nt][2] = __expf(s[nt][2] - m1);
            s[nt][3] = __expf(s[nt][3] - m1);
            sum0 += s[nt][0] + s[nt][1];
            sum1 += s[nt][2] + s[nt][3];
        }
        sum0 += __shfl_xor_sync(0xFFFFFFFFu, sum0, 1);
        sum0 += __shfl_xor_sync(0xFFFFFFFFu, sum0, 2);
        sum1 += __shfl_xor_sync(0xFFFFFFFFu, sum1, 1);
        sum1 += __shfl_xor_sync(0xFFFFFFFFu, sum1, 2);
        l0 = l0 * cr0 + sum0;
        l1 = l1 * cr1 + sum1;

#pragma unroll
        for (int dt = 0; dt < 8; dt++) {
            o[dt][0] *= cr0; o[dt][1] *= cr0;
            o[dt][2] *= cr1; o[dt][3] *= cr1;
        }

#pragma unroll
        for (int t = 0; t < 4; t++) {
            uint32_t ah[4], al[4];
            split2(s[2 * t][0],     s[2 * t][1],     ah[0], al[0]);
            split2(s[2 * t][2],     s[2 * t][3],     ah[1], al[1]);
            split2(s[2 * t + 1][0], s[2 * t + 1][1], ah[2], al[2]);
            split2(s[2 * t + 1][2], s[2 * t + 1][3], ah[3], al[3]);
#pragma unroll
            for (int dt = 0; dt < 8; dt++) {
                uint32_t bvh[2], bvl[2];
                const int vrow = t * 16 + (lane & 15);
                LDMATRIX_X2_TRANS(bvh[0], bvh[1], smemu32(&vh[vrow * FP + dt * 8]));
                LDMATRIX_X2_TRANS(bvl[0], bvl[1], smemu32(&vl[vrow * FP + dt * 8]));
                MMA_BF16(o[dt], ah, bvh);
                MMA_BF16(o[dt], al, bvh);
                MMA_BF16(o[dt], ah, bvl);
            }
        }
        __syncthreads();
    }

    const float inv0 = 1.f / l0, inv1 = 1.f / l1;
    const size_t tok0 = tokQ + wid * 16 + gq;
    const size_t base0 = tok0 * K3 + colQ;
    const size_t base1 = (tok0 + 8) * K3 + colQ;
#pragma unroll
    for (int dt = 0; dt < 8; dt++) {
        const int c = dt * 8 + qp2;
        uint32_t h0, lo0, h1, lo1;
        split2(o[dt][0] * inv0, o[dt][1] * inv0, h0, lo0);
        split2(o[dt][2] * inv1, o[dt][3] * inv1, h1, lo1);
        *(uint32_t*)&ycat[base0 + c]              = h0;
        *(uint32_t*)&ycat[base0 + C_EMB + c]      = h0;
        *(uint32_t*)&ycat[base0 + 2 * C_EMB + c]  = lo0;
        *(uint32_t*)&ycat[base1 + c]              = h1;
        *(uint32_t*)&ycat[base1 + C_EMB + c]      = h1;
        *(uint32_t*)&ycat[base1 + 2 * C_EMB + c]  = lo1;
    }
}

// ---------------------------------------------------------------------------
// Launch
// ---------------------------------------------------------------------------
extern "C" void kernel_launch(void* const* d_in, const int* in_sizes, int n_in,
                              void* d_out, int out_size)
{
    const float* x      = (const float*)d_in[0];
    const float* W_attn = (const float*)d_in[1];
    const float* b_attn = (const float*)d_in[2];
    const float* W_proj = (const float*)d_in[3];
    const float* b_proj = (const float*)d_in[4];
    float* out = (float*)d_out;

    __nv_bfloat16 *a1, *a2, *wa, *wp, *qh, *ql;
    cudaGetSymbolAddress((void**)&a1, g_a1);
    cudaGetSymbolAddress((void**)&a2, g_a2);
    cudaGetSymbolAddress((void**)&wa, g_wa);
    cudaGetSymbolAddress((void**)&wp, g_wp);
    cudaGetSymbolAddress((void**)&qh, g_qkvh);
    cudaGetSymbolAddress((void**)&ql, g_qkvl);

    const int flash_smem = (2 * 128 * FP + 8 * 64 * FP) * (int)sizeof(__nv_bfloat16);
    cudaFuncSetAttribute(flash_hmma_kernel,
                         cudaFuncAttributeMaxDynamicSharedMemorySize, flash_smem);
    cudaFuncSetAttribute(hmma_gemm_kernel<true>,
                         cudaFuncAttributeMaxDynamicSharedMemorySize, GEMM_SMEM);
    cudaFuncSetAttribute(hmma_gemm_kernel<false>,
                         cudaFuncAttributeMaxDynamicSharedMemorySize, GEMM_SMEM);

    // 0) preprocessing
    {
        int n = M_TOK * C_EMB;
        split_cat_kernel<<<(n + 255) / 256, 256>>>(x, a1, M_TOK, C_EMB);
    }
    {
        dim3 grid(C3 / 32, C_EMB / 32);
        splitT_cat_kernel<<<grid, dim3(32, 8)>>>(W_attn, wa, C_EMB, C3);
    }
    {
        dim3 grid(C_EMB / 32, C_EMB / 32);
        splitT_cat_kernel<<<grid, dim3(32, 8)>>>(W_proj, wp, C_EMB, C_EMB);
    }

    // 1) QKV GEMM -> bf16 hi/lo qkv
    {
        dim3 grid(C3 / GBN, M_TOK / GBM);
        hmma_gemm_kernel<true><<<grid, 256, GEMM_SMEM>>>(
            a1, wa, b_attn, nullptr, qh, ql, M_TOK, C3, K3);
    }

    // 2) Flash attention (HMMA) -> a2 in split-cat layout
    {
        dim3 grid(16, N_HEADS, 4);
        flash_hmma_kernel<<<grid, 256, flash_smem>>>(qh, ql, a2);
    }

    // 3) proj GEMM -> out fp32
    {
        dim3 grid(C_EMB / GBN, M_TOK / GBM);
        hmma_gemm_kernel<false><<<grid, 256, GEMM_SMEM>>>(
            a2, wp, b_proj, out, nullptr, nullptr, M_TOK, C_EMB, K3);
    }
}